// round 15
// baseline (speedup 1.0000x reference)
#include <cuda_runtime.h>
#include <cuda_fp16.h>

// LBP forward: out = 7.5 + 0.5 * sum_p 2^p * tanh(5*(samp_p - cen_p))
//
// Stage (R12/R14): TWO zero-padded fp16 copies scaled by 5 (PW=64 = 128B/row):
//   copy1[pl][r][j] = 5 * x[pl][r-1][j-4]   (centers, dx=0 samples)
//   copyB[pl][r][j] = 5 * x[pl][r-1][j-5]   (dx=-1 at +0; dx=+1 spans +0/+4)
// Main (R14 lane map + predicated merged loads): thread = (n,f,rb,quad q 0..15),
//   16 quads tile one 128B padded row -> every load/store touches the minimum
//   2 lines per warp. Per tap per row:
//     cv : aligned LDG.64 (center)
//     A  : aligned LDG.64 (sample base) -- PREDICATED OFF for null taps (reuse cv)
//     B  : aligned LDG.64 at +4B        -- PREDICATED ON only for dx=+1
//   window = dx>0 ? {A.y,B.x} : {A.x,A.y}.  No branches, batched per row.

#define N_  32
#define D_  64
#define H_  56
#define W_  56
#define F_  128
#define P_  4
#define HW_ (H_ * W_)
#define PW  64
#define PH  58
#define PPLANE (PW * PH)                  // 3712 halfs
#define NPLANES (N_ * D_)                 // 2048
#define SVOL (NPLANES * PPLANE)           // halfs per copy

__device__ __align__(16) __half g2[2 * NPLANES * PPLANE];   // 30.4 MB

// ---------------- stage ----------------
#define STAGE_TOTAL (NPLANES * PH * 8)

__global__ __launch_bounds__(256) void lbp_stage_kernel(const float* __restrict__ in)
{
    int idx = blockIdx.x * 256 + threadIdx.x;
    if (idx >= STAGE_TOTAL) return;
    int k  = idx & 7;
    int t  = idx >> 3;
    int r  = t % PH;
    int pl = t / PH;
    int row = r - 1;

    float wv[12];                 // wv[i] = x[8k-8+i]
#pragma unroll
    for (int i = 0; i < 12; i++) wv[i] = 0.f;

    if (row >= 0 && row < H_) {
        const float* __restrict__ rp = in + (size_t)pl * HW_ + row * W_;
        if (k >= 1) {
            float4 a = *reinterpret_cast<const float4*>(rp + 8 * k - 8);
            wv[0] = a.x; wv[1] = a.y; wv[2] = a.z; wv[3] = a.w;
            float4 b = *reinterpret_cast<const float4*>(rp + 8 * k - 4);
            wv[4] = b.x; wv[5] = b.y; wv[6] = b.z; wv[7] = b.w;
        }
        if (k <= 6) {
            float4 c = *reinterpret_cast<const float4*>(rp + 8 * k);
            wv[8] = c.x; wv[9] = c.y; wv[10] = c.z; wv[11] = c.w;
        }
    }

    __half2 h1[4], hB[4];
#pragma unroll
    for (int q = 0; q < 4; q++) {
        h1[q] = __floats2half2_rn(5.f * wv[4 + 2 * q], 5.f * wv[5 + 2 * q]);
        hB[q] = __floats2half2_rn(5.f * wv[3 + 2 * q], 5.f * wv[4 + 2 * q]);
    }
    size_t off = (size_t)pl * PPLANE + r * PW + 8 * k;
    *reinterpret_cast<uint4*>(g2 + off)                = *reinterpret_cast<uint4*>(h1);
    *reinterpret_cast<uint4*>(g2 + (size_t)SVOL + off) = *reinterpret_cast<uint4*>(hB);
}

// ---------------- main ----------------
__device__ __forceinline__ __half2 tanh_h2u(unsigned v) {
    asm("tanh.approx.f16x2 %0, %0;" : "+r"(v));
    return *reinterpret_cast<__half2*>(&v);
}

#define RB_ 14     // 4-row blocks per plane
#define NQ_ 16     // quads tiling the 128B padded row (q=0,15 pad)
#define TOTAL_ (N_ * F_ * RB_ * NQ_)   // 917,504 threads

__global__ __launch_bounds__(256, 6) void lbp_main_kernel(
    const int* __restrict__ kern,   // (F,P,2)
    const int* __restrict__ pm,     // (F,P)
    float*     __restrict__ out)
{
    int idx = blockIdx.x * 256 + threadIdx.x;
    if (idx >= TOTAL_) return;

    int q  = idx & 15;              // padded cols 4q..4q+3
    int t  = idx >> 4;
    int rb = t % RB_;
    t /= RB_;
    int f  = t & (F_ - 1);
    int n  = t >> 7;

    int r0 = rb * 4;

    int4 pmv = *reinterpret_cast<const int4*>(pm + f * P_);
    int4 k01 = *reinterpret_cast<const int4*>(kern + f * P_ * 2);
    int4 k23 = *reinterpret_cast<const int4*>(kern + f * P_ * 2 + 4);
    int cs[4]  = {pmv.x, pmv.y, pmv.z, pmv.w};
    int dys[4] = {k01.x - 1, k01.z - 1, k23.x - 1, k23.z - 1};
    int dxs[4] = {k01.y - 1, k01.w - 1, k23.y - 1, k23.w - 1};

    const int nbase = n * D_ * PPLANE;
    const int rcoff = (r0 + 1) * PW + 4 * q;    // 8B-aligned padded column

    int coff[4], soff[4];
    bool nul[4], pos[4];
#pragma unroll
    for (int p = 0; p < P_; p++) {
        int dx = dxs[p], dy = dys[p];
        int pb = nbase + cs[p] * PPLANE + rcoff;
        coff[p] = pb;
        soff[p] = pb + dy * PW + ((dx != 0) ? SVOL : 0);   // 8B-aligned
        nul[p]  = ((dx | dy) == 0);
        pos[p]  = (dx > 0);
    }

    __half2 z = __floats2half2_rn(0.f, 0.f);
    __half2 acc[8];
#pragma unroll
    for (int j = 0; j < 8; j++) acc[j] = z;

    const __half2 wp2s[4] = {
        __floats2half2_rn(0.5f, 0.5f), __floats2half2_rn(1.f, 1.f),
        __floats2half2_rn(2.f, 2.f),   __floats2half2_rn(4.f, 4.f)
    };

#pragma unroll
    for (int j = 0; j < 4; j++) {
        uint2 cv[4], A[4], B[4];
        // batched, predicated loads: worst case 12, expected ~8.9 per row
#pragma unroll
        for (int p = 0; p < P_; p++)
            cv[p] = *reinterpret_cast<const uint2*>(g2 + coff[p] + j * PW);
#pragma unroll
        for (int p = 0; p < P_; p++) {
            A[p] = cv[p];
            if (!nul[p]) A[p] = *reinterpret_cast<const uint2*>(g2 + soff[p] + j * PW);
        }
#pragma unroll
        for (int p = 0; p < P_; p++) {
            B[p] = A[p];
            if (pos[p]) B[p] = *reinterpret_cast<const uint2*>(g2 + soff[p] + j * PW + 4);
        }
#pragma unroll
        for (int p = 0; p < P_; p++) {
            unsigned s0 = pos[p] ? A[p].y : A[p].x;
            unsigned s1 = pos[p] ? B[p].x : A[p].y;
            __half2 d0 = __hsub2(*reinterpret_cast<__half2*>(&s0),
                                 *reinterpret_cast<__half2*>(&cv[p].x));
            __half2 d1 = __hsub2(*reinterpret_cast<__half2*>(&s1),
                                 *reinterpret_cast<__half2*>(&cv[p].y));
            acc[j * 2 + 0] = __hfma2(wp2s[p], tanh_h2u(*reinterpret_cast<unsigned*>(&d0)), acc[j * 2 + 0]);
            acc[j * 2 + 1] = __hfma2(wp2s[p], tanh_h2u(*reinterpret_cast<unsigned*>(&d1)), acc[j * 2 + 1]);
        }
    }

    if (q >= 1 && q <= 14) {                     // data quads only
        int w = 4 * q - 4;
        float* o = out + ((size_t)(n * F_ + f) * HW_ + r0 * W_ + w);
#pragma unroll
        for (int j = 0; j < 4; j++) {
            float2 lo = __half22float2(acc[j * 2 + 0]);
            float2 hi = __half22float2(acc[j * 2 + 1]);
            *reinterpret_cast<float4*>(o + j * W_) =
                make_float4(7.5f + lo.x, 7.5f + lo.y, 7.5f + hi.x, 7.5f + hi.y);
        }
    }
}

extern "C" void kernel_launch(void* const* d_in, const int* in_sizes, int n_in,
                              void* d_out, int out_size)
{
    const float* in   = (const float*)d_in[0];
    const int*   kern = (const int*)d_in[1];
    const int*   pm   = (const int*)d_in[2];
    float*       out  = (float*)d_out;

    lbp_stage_kernel<<<(STAGE_TOTAL + 255) / 256, 256>>>(in);
    lbp_main_kernel<<<(TOTAL_ + 255) / 256, 256>>>(kern, pm, out);
}

// round 17
// speedup vs baseline: 1.0009x; 1.0009x over previous
#include <cuda_runtime.h>
#include <cuda_fp16.h>

// LBP forward, single fused kernel:
//   out = 7.5 + 0.5 * sum_p 2^p * tanh(5*(samp_p - cen_p))
//
// Block = one (n, 4-row output slab). Loads the 64ch x 6row halo slab once,
// builds TWO pre-shifted x5 fp16 copies in SMEM:
//   copy1[c][jr][j] = 5 * x[c][r0-1+jr][j-4]   (centers, dx=0)
//   copyB[c][jr][j] = 5 * x[c][r0-1+jr][j-5]   (dx=-1 at +0; dx=+1 at +2)
// NOTE: copyB col 60 = 5*x[55] is real data (dx=+1 sample of out col 54) and
// is written explicitly by the q4==13 loader iteration (R16's missing piece).
// Compute: thread=(q 0..15, fg 0..31), 4 f's per thread, 4 rows x 4 cols each;
// branchless batched inner loop (null taps re-read center, tanh(0)=0).

#define N_  32
#define D_  64
#define H_  56
#define W_  56
#define F_  128
#define P_  4
#define HW_ (H_ * W_)

#define RS_   4                    // output rows per block
#define JR_   6                    // halo rows in smem (RS_+2)
#define PWs   64                   // smem padded row: 64 halfs = 128B
#define CST   (JR_ * PWs)          // channel stride in halfs (384)
#define COPY  (D_ * CST)           // one copy = 24576 halfs (48KB)
#define SMEM_HALFS (2 * COPY)      // 49152 halfs = 96KB
#define NSLAB (H_ / RS_)           // 14
#define NLOAD (D_ * JR_ * 14)      // 5376 float4 load items per block

__device__ __forceinline__ __half2 tanh_h2u(unsigned v) {
    asm("tanh.approx.f16x2 %0, %0;" : "+r"(v));
    return *reinterpret_cast<__half2*>(&v);
}

__global__ __launch_bounds__(512, 2) void lbp_fused_kernel(
    const float* __restrict__ in,
    const int*   __restrict__ kern,   // (F,P,2)
    const int*   __restrict__ pm,     // (F,P)
    float*       __restrict__ out)
{
    extern __shared__ __half sm[];    // [copy1 | copyB]
    int n    = blockIdx.x / NSLAB;
    int slab = blockIdx.x % NSLAB;
    int r0   = slab * RS_;
    int tid  = threadIdx.x;

    // ---- zero-fill smem (pads stay exact zeros) ----
    uint4 zz = make_uint4(0u, 0u, 0u, 0u);
    uint4* z4 = reinterpret_cast<uint4*>(sm);
#pragma unroll
    for (int i = 0; i < (SMEM_HALFS * 2 / 16 + 511) / 512; i++) {
        int k = i * 512 + tid;
        if (k < SMEM_HALFS * 2 / 16) z4[k] = zz;
    }
    __syncthreads();

    // ---- load + convert + build both copies ----
#pragma unroll
    for (int i = 0; i < (NLOAD + 511) / 512; i++) {
        int li = i * 512 + tid;
        if (li < NLOAD) {
            int c   = li / (JR_ * 14);
            int rem = li % (JR_ * 14);
            int jr  = rem / 14;
            int q4  = rem % 14;
            int row = r0 - 1 + jr;
            if (row >= 0 && row < H_) {
                const float* __restrict__ rp =
                    in + ((size_t)(n * D_ + c) * H_ + row) * W_ + 4 * q4;
                float4 v = *reinterpret_cast<const float4*>(rp);
                float xm1 = (q4 > 0) ? rp[-1] : 0.f;
                __half2 a  = __floats2half2_rn(5.f * v.x, 5.f * v.y);
                __half2 b  = __floats2half2_rn(5.f * v.z, 5.f * v.w);
                __half2 pa = __floats2half2_rn(5.f * xm1, 5.f * v.x);
                __half2 pb = __floats2half2_rn(5.f * v.y, 5.f * v.z);
                int j = c * CST + jr * PWs + 4 * q4 + 4;      // 8B-aligned
                uint2 u1, uB;
                u1.x = *reinterpret_cast<unsigned*>(&a);
                u1.y = *reinterpret_cast<unsigned*>(&b);
                uB.x = *reinterpret_cast<unsigned*>(&pa);
                uB.y = *reinterpret_cast<unsigned*>(&pb);
                *reinterpret_cast<uint2*>(sm + j)        = u1;
                *reinterpret_cast<uint2*>(sm + COPY + j) = uB;
                if (q4 == 13)                              // copyB col 60 = 5*x[55]
                    sm[COPY + c * CST + jr * PWs + 60] = __float2half_rn(5.f * v.w);
            }
        }
    }
    __syncthreads();

    // ---- compute: 4 f's per thread, 4 rows x 4 cols each ----
    int q  = tid & 15;                 // quad within 128B padded row
    int fg = tid >> 4;                 // 0..31
    int qc = (q == 15) ? 14 : q;       // clamp pad quad for addressing
    int hb = 4 * qc;                   // half-index base within row

    const __half2 wp2s[4] = {
        __floats2half2_rn(0.5f, 0.5f), __floats2half2_rn(1.f, 1.f),
        __floats2half2_rn(2.f, 2.f),   __floats2half2_rn(4.f, 4.f)
    };
    bool do_store = (q >= 1 && q <= 14);
    int  w = 4 * q - 4;

#pragma unroll
    for (int fi = 0; fi < 4; fi++) {
        int f = fg * 4 + fi;

        int4 pmv = *reinterpret_cast<const int4*>(pm + f * P_);
        int4 k01 = *reinterpret_cast<const int4*>(kern + f * P_ * 2);
        int4 k23 = *reinterpret_cast<const int4*>(kern + f * P_ * 2 + 4);
        int cs[4]  = {pmv.x, pmv.y, pmv.z, pmv.w};
        int dys[4] = {k01.x - 1, k01.z - 1, k23.x - 1, k23.z - 1};
        int dxs[4] = {k01.y - 1, k01.w - 1, k23.y - 1, k23.w - 1};

        int coff[4], soff[4];
#pragma unroll
        for (int p = 0; p < P_; p++) {
            int dx = dxs[p], dy = dys[p];
            coff[p] = cs[p] * CST + 1 * PWs + hb;                 // row jr=1
            soff[p] = cs[p] * CST + (1 + dy) * PWs + hb
                    + ((dx != 0) ? COPY : 0) + ((dx > 0) ? 2 : 0);
        }

        __half2 zh = __floats2half2_rn(0.f, 0.f);
        __half2 acc[8];
#pragma unroll
        for (int j = 0; j < 8; j++) acc[j] = zh;

#pragma unroll
        for (int j = 0; j < RS_; j++) {
            uint2    cv[4];
            unsigned sa[4], sb[4];
#pragma unroll
            for (int p = 0; p < P_; p++) {
                cv[p] = *reinterpret_cast<const uint2*>(sm + coff[p] + j * PWs);
                sa[p] = *reinterpret_cast<const unsigned*>(sm + soff[p] + j * PWs);
                sb[p] = *reinterpret_cast<const unsigned*>(sm + soff[p] + j * PWs + 2);
            }
#pragma unroll
            for (int p = 0; p < P_; p++) {
                __half2 d0 = __hsub2(*reinterpret_cast<__half2*>(&sa[p]),
                                     *reinterpret_cast<__half2*>(&cv[p].x));
                __half2 d1 = __hsub2(*reinterpret_cast<__half2*>(&sb[p]),
                                     *reinterpret_cast<__half2*>(&cv[p].y));
                acc[j * 2 + 0] = __hfma2(wp2s[p], tanh_h2u(*reinterpret_cast<unsigned*>(&d0)), acc[j * 2 + 0]);
                acc[j * 2 + 1] = __hfma2(wp2s[p], tanh_h2u(*reinterpret_cast<unsigned*>(&d1)), acc[j * 2 + 1]);
            }
        }

        if (do_store) {
            float* o = out + ((size_t)(n * F_ + f) * HW_ + r0 * W_ + w);
#pragma unroll
            for (int j = 0; j < RS_; j++) {
                float2 lo = __half22float2(acc[j * 2 + 0]);
                float2 hi = __half22float2(acc[j * 2 + 1]);
                *reinterpret_cast<float4*>(o + j * W_) =
                    make_float4(7.5f + lo.x, 7.5f + lo.y, 7.5f + hi.x, 7.5f + hi.y);
            }
        }
    }
}

extern "C" void kernel_launch(void* const* d_in, const int* in_sizes, int n_in,
                              void* d_out, int out_size)
{
    const float* in   = (const float*)d_in[0];
    const int*   kern = (const int*)d_in[1];
    const int*   pm   = (const int*)d_in[2];
    float*       out  = (float*)d_out;

    cudaFuncSetAttribute(lbp_fused_kernel,
                         cudaFuncAttributeMaxDynamicSharedMemorySize,
                         SMEM_HALFS * 2);

    lbp_fused_kernel<<<N_ * NSLAB, 512, SMEM_HALFS * 2>>>(in, kern, pm, out);
}